// round 15
// baseline (speedup 1.0000x reference)
#include <cuda_runtime.h>
#include <cuda_bf16.h>
#include <cstddef>
#include <cstdint>

typedef unsigned long long ull;

#define NN    2048
#define EE    8192
#define BB    32
#define TT    1500
#define EMBD  1280
#define HH    128
#define G4    512
#define SLOPE 0.01f

#define CHUNK_T 384 // pipeline chunk (4 chunks cover 1536 >= 1500)

// ---------------------------------------------------------------------------
// Scratch arena (offsets in floats).
// ---------------------------------------------------------------------------
#define OFF_GATES 0u
#define LEN_GATES 24576000u          /* 32*1500*512 */
#define OFF_MSG   24576000u
#define LEN_MSG   319488u            /* 2048*156 */
#define OFF_CNT   24895488u
#define LEN_CNT   2048u
#define OFF_ACAT  24897536u          /* 2048*312 */
#define OFF_WCAT  25536512u          /* 312*312 */
#define OFF_X1    25633856u          /* 2048*156 */
#define OFF_X2    25953344u          /* 2048*156 */
#define OFF_X3    26272832u          /* 2048*312 */
#define OFF_POOL  26911808u          /* 32*312 */
#define OFF_PROT  26921792u          /* 32*129 */
#define OFF_COMP  26925920u          /* 32*129 */
#define OFF_OUT1  27462560u          /* 32*1024 */
#define OFF_CAT1  27495328u          /* 32*1282 */
#define OFF_FC1O  27536352u          /* 32*512 */
#define OFF_TMP   27552736u          /* 132096*32 = 4227072 floats */
#define OFF_STATE 31779808u          /* 32*384: c,h,hsum per batch */
#define SCRATCH_TOTAL 31792096u

__device__ float g_scratch[SCRATCH_TOTAL];

// ---------------------------------------------------------------------------
// f32x2 + fast-activation + cluster helpers
// ---------------------------------------------------------------------------
__device__ __forceinline__ ull pk2(float lo, float hi) {
    ull r; asm("mov.b64 %0, {%1, %2};" : "=l"(r) : "f"(lo), "f"(hi)); return r;
}
__device__ __forceinline__ void upk2(ull v, float& lo, float& hi) {
    asm("mov.b64 {%0, %1}, %2;" : "=f"(lo), "=f"(hi) : "l"(v));
}
__device__ __forceinline__ void ffma2(ull& d, ull a, ull b) {
    asm("fma.rn.f32x2 %0, %1, %2, %0;" : "+l"(d) : "l"(a), "l"(b));
}
__device__ __forceinline__ float leakyf(float x) { return x > 0.f ? x : SLOPE * x; }

__device__ __forceinline__ float sigmoid_fast(float x) {
    return __fdividef(1.f, 1.f + __expf(-x));
}
__device__ __forceinline__ float tanh_fast(float x) {
    float ax = fabsf(x);
    float e  = __expf(2.f * ax);
    float tl = 1.f - __fdividef(2.f, e + 1.f);
    float t2 = x * x;
    float tp = x * (1.f + t2 * (-0.333333343f + t2 * (0.133333333f - 0.0539682545f * t2)));
    return (ax < 0.25f) ? tp : copysignf(tl, x);
}

__device__ __forceinline__ uint32_t smem_u32(const void* p) {
    uint32_t a;
    asm("{ .reg .u64 t; cvta.to.shared.u64 t, %1; cvt.u32.u64 %0, t; }"
        : "=r"(a) : "l"(p));
    return a;
}
__device__ __forceinline__ uint32_t ctarank() {
    uint32_t r; asm("mov.u32 %0, %%cluster_ctarank;" : "=r"(r)); return r;
}
__device__ __forceinline__ uint32_t mapa_u32(uint32_t a, uint32_t rank) {
    uint32_t r;
    asm("mapa.shared::cluster.u32 %0, %1, %2;" : "=r"(r) : "r"(a), "r"(rank));
    return r;
}
__device__ __forceinline__ void st_remote_f32(uint32_t ra, float v) {
    asm volatile("st.shared::cluster.f32 [%0], %1;" :: "r"(ra), "f"(v) : "memory");
}
__device__ __forceinline__ void mbar_init(uint32_t a, uint32_t cnt) {
    asm volatile("mbarrier.init.shared.b64 [%0], %1;" :: "r"(a), "r"(cnt) : "memory");
}
__device__ __forceinline__ void mbar_arrive_remote(uint32_t rbar) {
    asm volatile("mbarrier.arrive.release.cluster.shared::cluster.b64 _, [%0];"
                 :: "r"(rbar) : "memory");
}
__device__ __forceinline__ void mbar_wait_parity_cluster(uint32_t bar, uint32_t parity) {
    asm volatile(
        "{\n\t.reg .pred P;\n\t"
        "W_%=:\n\t"
        "mbarrier.try_wait.parity.acquire.cluster.shared::cta.b64 P, [%0], %1;\n\t"
        "@!P bra W_%=;\n\t}"
        :: "r"(bar), "r"(parity) : "memory");
}

// ---------------------------------------------------------------------------
// Chunked big GEMM: t in [t0,t0+384): gates[b,t,:] = data_pro[b,t,:]@Wih^T + bias
// grid (4,96): n-tile x (b = y/3, j = y%3).
// ---------------------------------------------------------------------------
__global__ void __launch_bounds__(256, 2) gemm_ih_kernel(
    const float* __restrict__ A, const float* __restrict__ W,
    const float* __restrict__ bih, const float* __restrict__ bhh,
    const int* __restrict__ lens, float* __restrict__ C, int t0)
{
    const int b = blockIdx.y / 3;
    const int tbase = t0 + (blockIdx.y % 3) * 128;
    const int n0 = blockIdx.x * 128;
    const int tid = threadIdx.x;
    const int lenb = lens[b];

    int pred = 0;
    if (tid < 128) pred = (tbase + tid < lenb);
    if (!__syncthreads_or(pred)) return;

    __shared__ float As[8][128];
    __shared__ float Bs[8][128];

    const int lr = tid >> 1;
    const int lc = (tid & 1) << 2;
    const int tx = tid & 15;
    const int ty = tid >> 4;

    const int tA = min(tbase + lr, TT - 1);
    const float* Ap = A + ((size_t)b * TT + tA) * EMBD + lc;
    const float* Wp = W + (size_t)(n0 + lr) * EMBD + lc;

    ull acc[8][4];
#pragma unroll
    for (int i = 0; i < 8; ++i)
#pragma unroll
        for (int j = 0; j < 4; ++j) acc[i][j] = 0ull;

    float4 an = *(const float4*)Ap;
    float4 wn = *(const float4*)Wp;

    for (int kt = 0; kt < EMBD / 8; ++kt) {
        As[lc + 0][lr] = an.x; As[lc + 1][lr] = an.y;
        As[lc + 2][lr] = an.z; As[lc + 3][lr] = an.w;
        Bs[lc + 0][lr] = wn.x; Bs[lc + 1][lr] = wn.y;
        Bs[lc + 2][lr] = wn.z; Bs[lc + 3][lr] = wn.w;
        __syncthreads();
        if (kt + 1 < EMBD / 8) {
            an = *(const float4*)(Ap + (size_t)(kt + 1) * 8);
            wn = *(const float4*)(Wp + (size_t)(kt + 1) * 8);
        }
#pragma unroll
        for (int k = 0; k < 8; ++k) {
            ulonglong2 ub0 = *(const ulonglong2*)&Bs[k][tx * 4];
            ulonglong2 ub1 = *(const ulonglong2*)&Bs[k][64 + tx * 4];
            ull b0 = ub0.x, b1 = ub0.y, b2 = ub1.x, b3 = ub1.y;
            float4 af0 = *(const float4*)&As[k][ty * 8];
            float4 af1 = *(const float4*)&As[k][ty * 8 + 4];
            float ar[8] = { af0.x, af0.y, af0.z, af0.w, af1.x, af1.y, af1.z, af1.w };
#pragma unroll
            for (int i = 0; i < 8; ++i) {
                ull ap = pk2(ar[i], ar[i]);
                ffma2(acc[i][0], ap, b0);
                ffma2(acc[i][1], ap, b1);
                ffma2(acc[i][2], ap, b2);
                ffma2(acc[i][3], ap, b3);
            }
        }
        __syncthreads();
    }

    const int na = n0 + tx * 4;
    const int nb = n0 + 64 + tx * 4;
    float bsa[4], bsb[4];
#pragma unroll
    for (int j = 0; j < 4; ++j) {
        bsa[j] = bih[na + j] + bhh[na + j];
        bsb[j] = bih[nb + j] + bhh[nb + j];
    }

#pragma unroll
    for (int i = 0; i < 8; ++i) {
        int t = tbase + ty * 8 + i;
        if (t < lenb) {
            size_t r = (size_t)b * TT + t;
            float v0, v1, v2, v3, v4, v5, v6, v7;
            upk2(acc[i][0], v0, v1); upk2(acc[i][1], v2, v3);
            upk2(acc[i][2], v4, v5); upk2(acc[i][3], v6, v7);
            float4 w0 = make_float4(v0 + bsa[0], v1 + bsa[1], v2 + bsa[2], v3 + bsa[3]);
            float4 w1 = make_float4(v4 + bsb[0], v5 + bsb[1], v6 + bsb[2], v7 + bsb[3]);
            *(float4*)&C[r * G4 + na] = w0;
            *(float4*)&C[r * G4 + nb] = w1;
        }
    }
}

// ---------------------------------------------------------------------------
// LSTM chunk, 2-CTA cluster per batch. grid = 64, cluster (2,1,1).
// CTA rank r owns hh in [r*64, r*64+64) => 256 gate rows; 512 threads each
// compute a HALF row (64 cols) with ALL weights in registers (32 f32x2).
// lane layout: lane = hhq*8 + gt*2 + half  (hhq=lane>>3, gt=(lane>>1)&3,
// half=lane&1); hh = rank*64 + warp*4 + hhq; row = gt*128 + hh.
// Halves combine via shfl_xor(1); gates gather via shfl. Per step each CTA's
// 64 writer lanes store new h locally + into the peer's double-buffered h
// (st.shared::cluster) and arrive on the peer's mbarrier (count 64).
// ---------------------------------------------------------------------------
__global__ void __launch_bounds__(512, 1) __cluster_dims__(2, 1, 1)
lstm_cluster_kernel(
    const float* __restrict__ gates, const float* __restrict__ Whh,
    const int* __restrict__ lens, float* __restrict__ state,
    float* __restrict__ prot, int t0, int t1, int first, int last)
{
    __shared__ __align__(16) float hbuf[2][HH];
    __shared__ __align__(8) ull mbar;

    const int tid  = threadIdx.x;
    const int lane = tid & 31;
    const int warp = tid >> 5;
    const uint32_t rank = ctarank();
    const int b = blockIdx.x >> 1;

    const int half = lane & 1;
    const int gt   = (lane >> 1) & 3;
    const int hh   = (int)rank * 64 + warp * 4 + (lane >> 3);
    const int row  = gt * HH + hh;
    const bool writer = (gt == 0 && half == 0);

    // all 64 weight columns of this half-row in registers
    ull wr[32];
    const float* wrow = Whh + (size_t)row * HH + half * 64;
#pragma unroll
    for (int j = 0; j < 32; ++j)
        wr[j] = *(const ull*)(wrow + 2 * j);

    float* st = state + b * 384;

    if (tid == 0) mbar_init(smem_u32(&mbar), 64);
    if (tid < HH) hbuf[0][tid] = first ? 0.f : st[HH + tid];
    __syncthreads();
    asm volatile("barrier.cluster.arrive.aligned;" ::: "memory");
    asm volatile("barrier.cluster.wait.aligned;" ::: "memory");

    const uint32_t peer = rank ^ 1u;
    const uint32_t r_mbar  = mapa_u32(smem_u32(&mbar), peer);
    const uint32_t r_slot0 = mapa_u32(smem_u32(&hbuf[0][hh]), peer);
    const uint32_t r_slot1 = mapa_u32(smem_u32(&hbuf[1][hh]), peer);
    const uint32_t bar_a   = smem_u32(&mbar);

    float c      = first ? 0.f : st[hh];
    float hsum   = first ? 0.f : st[256 + hh];
    float hn_cur = first ? 0.f : st[HH + hh];

    const int len = lens[b];
    const int te = min(len, t1);
    const float* grow = gates + (size_t)b * TT * G4 + row;

    if (t0 < te) {
        int buf = 0;
        float gx = grow[(size_t)t0 * G4];
        for (int t = t0; t < te; ++t) {
            if (t > t0)
                mbar_wait_parity_cluster(bar_a, (uint32_t)((t - t0 - 1) & 1));

            int tn = (t + 1 < te) ? t + 1 : te - 1;
            float gxn = grow[(size_t)tn * G4];

            const ulonglong2* h4 = (const ulonglong2*)&hbuf[buf][half * 64];
            ull a0 = 0ull, a1 = 0ull;
#pragma unroll
            for (int p = 0; p < 16; ++p) {
                ulonglong2 hv = h4[p];
                ffma2(a0, hv.x, wr[2 * p]);
                ffma2(a1, hv.y, wr[2 * p + 1]);
            }
            float l0, u0, l1, u1;
            upk2(a0, l0, u0); upk2(a1, l1, u1);
            float v = (l0 + u0) + (l1 + u1);
            v += __shfl_xor_sync(0xFFFFFFFFu, v, 1);   // combine halves
            float a = v + gx;
            float av = (gt == 2) ? tanh_fast(a) : sigmoid_fast(a);

            const int bse = lane & ~7;
            float iv = __shfl_sync(0xFFFFFFFFu, av, bse + 0);
            float fv = __shfl_sync(0xFFFFFFFFu, av, bse + 2);
            float gv = __shfl_sync(0xFFFFFFFFu, av, bse + 4);
            float ov = __shfl_sync(0xFFFFFFFFu, av, bse + 6);
            c = fv * c + iv * gv;
            float hn = ov * tanh_fast(c);

            if (t + 1 < te) {
                int nbuf = buf ^ 1;
                if (writer) {
                    hbuf[nbuf][hh] = hn;
                    st_remote_f32(nbuf ? r_slot1 : r_slot0, hn);
                    mbar_arrive_remote(r_mbar);
                }
                __syncthreads();
                buf = nbuf;
            }
            if (writer) { hsum += hn; hn_cur = hn; }
            gx = gxn;
        }
    }

    if (last) {
        if (writer) prot[b * 129 + hh] = hsum * (1.f / (float)TT);
        if (rank == 0 && tid == 0) prot[b * 129 + HH] = 1.f;
    } else if (writer) {
        st[hh] = c;
        st[HH + hh] = hn_cur;
        st[256 + hh] = hsum;
    }
}

// ---------------------------------------------------------------------------
// Generic tiled GEMM: C[M,Nc] = A[M,K] @ W[Nc,K]^T + bias (optional leaky).
// ---------------------------------------------------------------------------
__global__ void gemm_at_kernel(
    const float* __restrict__ A, const float* __restrict__ W,
    const float* __restrict__ bias, float* __restrict__ C,
    int M, int Nc, int K, int ldc, int do_leaky)
{
    __shared__ float As[32][33];
    __shared__ float Ws[32][33];
    const int n0 = blockIdx.x * 32;
    const int m0 = blockIdx.y * 32;
    const int tid = threadIdx.x;
    const int o = tid & 31;
    const int rq = tid >> 5;

    float acc[4] = {0.f, 0.f, 0.f, 0.f};

    for (int k0 = 0; k0 < K; k0 += 32) {
#pragma unroll
        for (int p = 0; p < 4; ++p) {
            int idx = tid + p * 256;
            int i = idx >> 5;
            int kk = idx & 31;
            int ak = k0 + kk;
            int ar = m0 + i;
            As[i][kk] = (ar < M && ak < K) ? A[(size_t)ar * K + ak] : 0.f;
            int wr_ = n0 + i;
            Ws[i][kk] = (wr_ < Nc && ak < K) ? W[(size_t)wr_ * K + ak] : 0.f;
        }
        __syncthreads();
#pragma unroll
        for (int kk = 0; kk < 32; ++kk) {
            float w = Ws[o][kk];
#pragma unroll
            for (int q = 0; q < 4; ++q)
                acc[q] += As[rq + q * 8][kk] * w;
        }
        __syncthreads();
    }

    int n = n0 + o;
    if (n < Nc) {
        float bv = bias[n];
#pragma unroll
        for (int q = 0; q < 4; ++q) {
            int m = m0 + rq + q * 8;
            if (m < M) {
                float v = acc[q] + bv;
                if (do_leaky) v = leakyf(v);
                C[(size_t)m * ldc + n] = v;
            }
        }
    }
}

// ---------------------------------------------------------------------------
// mix stage A: tmp[r, b] = sum_j mix_W[r*129 + j] * comp[b, j]
// ---------------------------------------------------------------------------
__global__ void __launch_bounds__(256, 2) mixA_kernel(
    const float* __restrict__ W, const float* __restrict__ comp,
    float* __restrict__ tmp)
{
    extern __shared__ float dsm[];
    float* Ws = dsm;              // [128][133]
    float* cs = dsm + 128 * 133;  // [129][32]

    const int tid = threadIdx.x;
    const int r0 = blockIdx.x * 128;

    for (int idx = tid; idx < 129 * 32; idx += 256) {
        int j = idx >> 5;
        int b = idx & 31;
        cs[j * 32 + b] = comp[b * 129 + j];
    }
    const float4* Wp = (const float4*)(W + (size_t)r0 * 129);
    for (int idx = tid; idx < 4128; idx += 256) {
        float4 v = Wp[idx];
        int e = idx * 4;
        float vv[4] = { v.x, v.y, v.z, v.w };
#pragma unroll
        for (int q = 0; q < 4; ++q) {
            int ee = e + q;
            int rr = ee / 129;
            int kk = ee - rr * 129;
            Ws[rr * 133 + kk] = vv[q];
        }
    }
    __syncthreads();

    const int r  = tid >> 1;
    const int bh = (tid & 1) << 4;
    ull acc[8];
#pragma unroll
    for (int q = 0; q < 8; ++q) acc[q] = 0ull;

    const float* wrow = Ws + r * 133;
    for (int k = 0; k < 129; ++k) {
        float w = wrow[k];
        ull wp = pk2(w, w);
        const ull* cp = (const ull*)&cs[k * 32 + bh];
#pragma unroll
        for (int q = 0; q < 8; ++q) ffma2(acc[q], wp, cp[q]);
    }

    float* outp = tmp + (size_t)(r0 + r) * 32 + bh;
#pragma unroll
    for (int q = 0; q < 8; ++q) {
        float lo, hi;
        upk2(acc[q], lo, hi);
        *(float2*)&outp[2 * q] = make_float2(lo, hi);
    }
}

// ---------------------------------------------------------------------------
// mix stage B: out1[b, n] = leaky( sum_i tmp[n*129+i, b] * prot[b, i] + mix_b[n] )
// ---------------------------------------------------------------------------
__global__ void mixB_kernel(
    const float* __restrict__ tmp, const float* __restrict__ prot,
    const float* __restrict__ mix_b, float* __restrict__ out1)
{
    __shared__ float ps[32 * 129];
    __shared__ float part[4][32];
    const int n = blockIdx.x;
    const int tid = threadIdx.x;
    const int lane = tid & 31;
    const int w = tid >> 5;

    for (int idx = tid; idx < 32 * 129; idx += 128) ps[idx] = prot[idx];
    __syncthreads();

    float acc = 0.f;
    const float* tp = tmp + (size_t)n * 129 * 32 + lane;
    const float* pp = ps + lane * 129;
    for (int i = w; i < 129; i += 4)
        acc += tp[i * 32] * pp[i];
    part[w][lane] = acc;
    __syncthreads();
    if (w == 0) {
        float v = part[0][lane] + part[1][lane] + part[2][lane] + part[3][lane] + mix_b[n];
        out1[lane * 1024 + n] = leakyf(v);
    }
}

// ---------------------------------------------------------------------------
// Small kernels
// ---------------------------------------------------------------------------
__global__ void zero_kernel(float* p, int n) {
    int i = blockIdx.x * blockDim.x + threadIdx.x;
    if (i < n) p[i] = 0.f;
}

__global__ void count_kernel(const int* __restrict__ dst, float* __restrict__ cnt) {
    int e = blockIdx.x * blockDim.x + threadIdx.x;
    if (e < EE) atomicAdd(&cnt[dst[e]], 1.f);
}

__global__ void scatter_kernel(const float* __restrict__ x,
                               const int* __restrict__ src, const int* __restrict__ dst,
                               float* __restrict__ msg, int din) {
    int idx = blockIdx.x * blockDim.x + threadIdx.x;
    if (idx >= EE * din) return;
    int e = idx / din;
    int d = idx - e * din;
    atomicAdd(&msg[(size_t)dst[e] * din + d], x[(size_t)src[e] * din + d]);
}

__global__ void build_acat_kernel(const float* __restrict__ msg, const float* __restrict__ cnt,
                                  const float* __restrict__ x, float* __restrict__ acat, int din) {
    int idx = blockIdx.x * blockDim.x + threadIdx.x;
    if (idx >= NN * din) return;
    int n = idx / din;
    int d = idx - n * din;
    float cdiv = fmaxf(cnt[n], 1.f);
    acat[(size_t)n * 2 * din + d] = msg[idx] / cdiv;
    acat[(size_t)n * 2 * din + din + d] = x[idx];
}

__global__ void build_wcat_kernel(const float* __restrict__ Wl, const float* __restrict__ Wr,
                                  float* __restrict__ wcat, int dout, int din) {
    int idx = blockIdx.x * blockDim.x + threadIdx.x;
    if (idx >= dout * din) return;
    int oo = idx / din;
    int d = idx - oo * din;
    wcat[(size_t)oo * 2 * din + d] = Wl[idx];
    wcat[(size_t)oo * 2 * din + din + d] = Wr[idx];
}

__global__ void pool_kernel(const float* __restrict__ x3, float* __restrict__ pool) {
    int idx = blockIdx.x * blockDim.x + threadIdx.x;
    if (idx >= BB * 312) return;
    int b = idx / 312;
    int d = idx - b * 312;
    float m = -3.4e38f;
    int base = b * (NN / BB);
#pragma unroll 4
    for (int n = 0; n < NN / BB; ++n)
        m = fmaxf(m, x3[(size_t)(base + n) * 312 + d]);
    pool[idx] = m;
}

__global__ void set_ones_kernel(float* __restrict__ comp) {
    int t = threadIdx.x;
    if (t < BB) comp[t * 129 + 128] = 1.f;
}

__global__ void cat1_kernel(const float* __restrict__ out1, const float* __restrict__ prot,
                            const float* __restrict__ comp, float* __restrict__ cat1) {
    int idx = blockIdx.x * blockDim.x + threadIdx.x;
    if (idx >= BB * 1282) return;
    int b = idx / 1282;
    int d = idx - b * 1282;
    float v;
    if (d < 1024)       v = out1[b * 1024 + d];
    else if (d < 1153)  v = prot[b * 129 + (d - 1024)];
    else                v = comp[b * 129 + (d - 1153)];
    cat1[idx] = v;
}

__global__ void fc2_kernel(const float* __restrict__ x, const float* __restrict__ W,
                           const float* __restrict__ bias, float* __restrict__ out) {
    __shared__ float red[512];
    int b = blockIdx.x;
    int t = threadIdx.x;
    red[t] = x[(size_t)b * 512 + t] * W[t];
    __syncthreads();
    for (int s = 256; s > 0; s >>= 1) {
        if (t < s) red[t] += red[t + s];
        __syncthreads();
    }
    if (t == 0) out[b] = red[0] + bias[0];
}

// ---------------------------------------------------------------------------
// Launch. s0: gemm chunks -> events. sP: lstm cluster chunks. sB: molecule.
// All stream/event resources created ONCE on the first call.
// ---------------------------------------------------------------------------
extern "C" void kernel_launch(void* const* d_in, const int* in_sizes, int n_in,
                              void* d_out, int out_size)
{
    const float* mol_x    = (const float*)d_in[0];
    const float* data_pro = (const float*)d_in[1];
    const int*   ei       = (const int*)d_in[2];
    const int*   lens     = (const int*)d_in[4];
    const float* s1_Wl = (const float*)d_in[5];
    const float* s1_bl = (const float*)d_in[6];
    const float* s1_Wr = (const float*)d_in[7];
    const float* s2_Wl = (const float*)d_in[8];
    const float* s2_bl = (const float*)d_in[9];
    const float* s2_Wr = (const float*)d_in[10];
    const float* s3_Wl = (const float*)d_in[11];
    const float* s3_bl = (const float*)d_in[12];
    const float* s3_Wr = (const float*)d_in[13];
    const float* fcg_W = (const float*)d_in[14];
    const float* fcg_b = (const float*)d_in[15];
    const float* Wih   = (const float*)d_in[16];
    const float* Whh   = (const float*)d_in[17];
    const float* bih   = (const float*)d_in[18];
    const float* bhh   = (const float*)d_in[19];
    const float* mix_W = (const float*)d_in[20];
    const float* mix_b = (const float*)d_in[21];
    const float* fc1_W = (const float*)d_in[22];
    const float* fc1_b = (const float*)d_in[23];
    const float* fc2_W = (const float*)d_in[24];
    const float* fc2_b = (const float*)d_in[25];
    float* out = (float*)d_out;

    float* base = nullptr;
    cudaGetSymbolAddress((void**)&base, g_scratch);
    float* gates = base + OFF_GATES;
    float* msg   = base + OFF_MSG;
    float* cnt   = base + OFF_CNT;
    float* acat  = base + OFF_ACAT;
    float* wcat  = base + OFF_WCAT;
    float* x1    = base + OFF_X1;
    float* x2    = base + OFF_X2;
    float* x3    = base + OFF_X3;
    float* pool  = base + OFF_POOL;
    float* prot  = base + OFF_PROT;
    float* comp  = base + OFF_COMP;
    float* out1  = base + OFF_OUT1;
    float* cat1  = base + OFF_CAT1;
    float* fc1o  = base + OFF_FC1O;
    float* tmpA  = base + OFF_TMP;
    float* state = base + OFF_STATE;

    const int* src = ei;
    const int* dst = ei + EE;

    const int mixA_smem = (128 * 133 + 129 * 32) * 4;         // 84608 B

    static cudaStream_t sP = nullptr, sB = nullptr;
    static cudaEvent_t evFork = nullptr, evJoinP = nullptr, evJoinB = nullptr;
    static cudaEvent_t evG[4] = {nullptr, nullptr, nullptr, nullptr};
    if (sP == nullptr) {
        cudaFuncSetAttribute(mixA_kernel, cudaFuncAttributeMaxDynamicSharedMemorySize, mixA_smem);
        cudaStreamCreateWithFlags(&sP, cudaStreamNonBlocking);
        cudaStreamCreateWithFlags(&sB, cudaStreamNonBlocking);
        cudaEventCreateWithFlags(&evFork,  cudaEventDisableTiming);
        cudaEventCreateWithFlags(&evJoinP, cudaEventDisableTiming);
        cudaEventCreateWithFlags(&evJoinB, cudaEventDisableTiming);
        for (int i = 0; i < 4; ++i)
            cudaEventCreateWithFlags(&evG[i], cudaEventDisableTiming);
    }

    // fork molecule stream
    cudaEventRecord(evFork, 0);
    cudaStreamWaitEvent(sB, evFork, 0);

    // --- protein pipeline: gemm chunk k (s0) -> event -> lstm chunk k (sP) ---
    for (int k = 0; k < 4; ++k) {
        gemm_ih_kernel<<<dim3(4, 96), 256>>>(data_pro, Wih, bih, bhh, lens, gates, k * CHUNK_T);
        cudaEventRecord(evG[k], 0);
        cudaStreamWaitEvent(sP, evG[k], 0);
        lstm_cluster_kernel<<<2 * BB, 512, 0, sP>>>(
            gates, Whh, lens, state, prot,
            k * CHUNK_T, (k == 3) ? TT : (k + 1) * CHUNK_T,
            (k == 0) ? 1 : 0, (k == 3) ? 1 : 0);
    }

    // --- molecule branch + mixA (sB, hidden under protein) ---
    zero_kernel<<<(LEN_MSG + LEN_CNT + 255) / 256, 256, 0, sB>>>(msg, LEN_MSG + LEN_CNT);
    count_kernel<<<(EE + 255) / 256, 256, 0, sB>>>(dst, cnt);
    scatter_kernel<<<(EE * 78 + 255) / 256, 256, 0, sB>>>(mol_x, src, dst, msg, 78);
    build_acat_kernel<<<(NN * 78 + 255) / 256, 256, 0, sB>>>(msg, cnt, mol_x, acat, 78);
    build_wcat_kernel<<<(156 * 78 + 255) / 256, 256, 0, sB>>>(s1_Wl, s1_Wr, wcat, 156, 78);
    gemm_at_kernel<<<dim3(5, 64), 256, 0, sB>>>(acat, wcat, s1_bl, x1, NN, 156, 156, 156, 1);

    zero_kernel<<<(LEN_MSG + 255) / 256, 256, 0, sB>>>(msg, LEN_MSG);
    scatter_kernel<<<(EE * 156 + 255) / 256, 256, 0, sB>>>(x1, src, dst, msg, 156);
    build_acat_kernel<<<(NN * 156 + 255) / 256, 256, 0, sB>>>(msg, cnt, x1, acat, 156);
    build_wcat_kernel<<<(156 * 156 + 255) / 256, 256, 0, sB>>>(s2_Wl, s2_Wr, wcat, 156, 156);
    gemm_at_kernel<<<dim3(5, 64), 256, 0, sB>>>(acat, wcat, s2_bl, x2, NN, 156, 312, 156, 1);

    zero_kernel<<<(LEN_MSG + 255) / 256, 256, 0, sB>>>(msg, LEN_MSG);
    scatter_kernel<<<(EE * 156 + 255) / 256, 256, 0, sB>>>(x2, src, dst, msg, 156);
    build_acat_kernel<<<(NN * 156 + 255) / 256, 256, 0, sB>>>(msg, cnt, x2, acat, 156);
    build_wcat_kernel<<<(312 * 156 + 255) / 256, 256, 0, sB>>>(s3_Wl, s3_Wr, wcat, 312, 156);
    gemm_at_kernel<<<dim3(10, 64), 256, 0, sB>>>(acat, wcat, s3_bl, x3, NN, 312, 312, 312, 1);

    pool_kernel<<<(BB * 312 + 255) / 256, 256, 0, sB>>>(x3, pool);
    gemm_at_kernel<<<dim3(4, 1), 256, 0, sB>>>(pool, fcg_W, fcg_b, comp, BB, 128, 312, 129, 0);
    set_ones_kernel<<<1, 32, 0, sB>>>(comp);
    mixA_kernel<<<1032, 256, mixA_smem, sB>>>(mix_W, comp, tmpA);

    // join both branches into s0
    cudaEventRecord(evJoinP, sP);
    cudaStreamWaitEvent(0, evJoinP, 0);
    cudaEventRecord(evJoinB, sB);
    cudaStreamWaitEvent(0, evJoinB, 0);

    // --- fusion head (s0) ---
    mixB_kernel<<<1024, 128>>>(tmpA, prot, mix_b, out1);
    cat1_kernel<<<(BB * 1282 + 255) / 256, 256>>>(out1, prot, comp, cat1);
    gemm_at_kernel<<<dim3(16, 1), 256>>>(cat1, fc1_W, fc1_b, fc1o, BB, 512, 1282, 512, 1);
    fc2_kernel<<<BB, 512>>>(fc1o, fc2_W, fc2_b, out);
}

// round 16
// speedup vs baseline: 2.0444x; 2.0444x over previous
#include <cuda_runtime.h>
#include <cuda_bf16.h>
#include <cstddef>
#include <cstdint>

typedef unsigned long long ull;

#define NN    2048
#define EE    8192
#define BB    32
#define TT    1500
#define EMBD  1280
#define HH    128
#define G4    512
#define SLOPE 0.01f

#define CHUNK_T 384 // pipeline chunk (4 chunks cover 1536 >= 1500)

// ---------------------------------------------------------------------------
// Scratch arena (offsets in floats).
// ---------------------------------------------------------------------------
#define OFF_GATES 0u
#define LEN_GATES 24576000u          /* 32*1500*512 */
#define OFF_MSG   24576000u
#define LEN_MSG   319488u            /* 2048*156 */
#define OFF_CNT   24895488u
#define LEN_CNT   2048u
#define OFF_ACAT  24897536u          /* 2048*312 */
#define OFF_WCAT  25536512u          /* 312*312 */
#define OFF_X1    25633856u          /* 2048*156 */
#define OFF_X2    25953344u          /* 2048*156 */
#define OFF_X3    26272832u          /* 2048*312 */
#define OFF_POOL  26911808u          /* 32*312 */
#define OFF_PROT  26921792u          /* 32*129 */
#define OFF_COMP  26925920u          /* 32*129 */
#define OFF_OUT1  27462560u          /* 32*1024 */
#define OFF_CAT1  27495328u          /* 32*1282 */
#define OFF_FC1O  27536352u          /* 32*512 */
#define OFF_TMP   27552736u          /* 132096*32 = 4227072 floats */
#define OFF_STATE 31779808u          /* 32*384: c,h,hsum per batch */
#define SCRATCH_TOTAL 31792096u

__device__ float g_scratch[SCRATCH_TOTAL];

// ---------------------------------------------------------------------------
// f32x2 + fast-activation helpers
// ---------------------------------------------------------------------------
__device__ __forceinline__ ull pk2(float lo, float hi) {
    ull r; asm("mov.b64 %0, {%1, %2};" : "=l"(r) : "f"(lo), "f"(hi)); return r;
}
__device__ __forceinline__ void upk2(ull v, float& lo, float& hi) {
    asm("mov.b64 {%0, %1}, %2;" : "=f"(lo), "=f"(hi) : "l"(v));
}
__device__ __forceinline__ void ffma2(ull& d, ull a, ull b) {
    asm("fma.rn.f32x2 %0, %1, %2, %0;" : "+l"(d) : "l"(a), "l"(b));
}
__device__ __forceinline__ float leakyf(float x) { return x > 0.f ? x : SLOPE * x; }

__device__ __forceinline__ float sigmoid_fast(float x) {
    return __fdividef(1.f, 1.f + __expf(-x));
}
// Precision-safe fast tanh: odd poly (|x|<0.25, err ~1e-7), else 1-2/(e^2x+1).
__device__ __forceinline__ float tanh_fast(float x) {
    float ax = fabsf(x);
    float e  = __expf(2.f * ax);
    float tl = 1.f - __fdividef(2.f, e + 1.f);
    float t2 = x * x;
    float tp = x * (1.f + t2 * (-0.333333343f + t2 * (0.133333333f - 0.0539682545f * t2)));
    return (ax < 0.25f) ? tp : copysignf(tl, x);
}

// ---------------------------------------------------------------------------
// Chunked big GEMM: t in [t0,t0+384): gates[b,t,:] = data_pro[b,t,:]@Wih^T + bias
// grid (4,96): n-tile x (b = y/3, j = y%3).
// ---------------------------------------------------------------------------
__global__ void __launch_bounds__(256, 2) gemm_ih_kernel(
    const float* __restrict__ A, const float* __restrict__ W,
    const float* __restrict__ bih, const float* __restrict__ bhh,
    const int* __restrict__ lens, float* __restrict__ C, int t0)
{
    const int b = blockIdx.y / 3;
    const int tbase = t0 + (blockIdx.y % 3) * 128;
    const int n0 = blockIdx.x * 128;
    const int tid = threadIdx.x;
    const int lenb = lens[b];

    int pred = 0;
    if (tid < 128) pred = (tbase + tid < lenb);
    if (!__syncthreads_or(pred)) return;

    __shared__ float As[8][128];
    __shared__ float Bs[8][128];

    const int lr = tid >> 1;
    const int lc = (tid & 1) << 2;
    const int tx = tid & 15;
    const int ty = tid >> 4;

    const int tA = min(tbase + lr, TT - 1);
    const float* Ap = A + ((size_t)b * TT + tA) * EMBD + lc;
    const float* Wp = W + (size_t)(n0 + lr) * EMBD + lc;

    ull acc[8][4];
#pragma unroll
    for (int i = 0; i < 8; ++i)
#pragma unroll
        for (int j = 0; j < 4; ++j) acc[i][j] = 0ull;

    float4 an = *(const float4*)Ap;
    float4 wn = *(const float4*)Wp;

    for (int kt = 0; kt < EMBD / 8; ++kt) {
        As[lc + 0][lr] = an.x; As[lc + 1][lr] = an.y;
        As[lc + 2][lr] = an.z; As[lc + 3][lr] = an.w;
        Bs[lc + 0][lr] = wn.x; Bs[lc + 1][lr] = wn.y;
        Bs[lc + 2][lr] = wn.z; Bs[lc + 3][lr] = wn.w;
        __syncthreads();
        if (kt + 1 < EMBD / 8) {
            an = *(const float4*)(Ap + (size_t)(kt + 1) * 8);
            wn = *(const float4*)(Wp + (size_t)(kt + 1) * 8);
        }
#pragma unroll
        for (int k = 0; k < 8; ++k) {
            ulonglong2 ub0 = *(const ulonglong2*)&Bs[k][tx * 4];
            ulonglong2 ub1 = *(const ulonglong2*)&Bs[k][64 + tx * 4];
            ull b0 = ub0.x, b1 = ub0.y, b2 = ub1.x, b3 = ub1.y;
            float4 af0 = *(const float4*)&As[k][ty * 8];
            float4 af1 = *(const float4*)&As[k][ty * 8 + 4];
            float ar[8] = { af0.x, af0.y, af0.z, af0.w, af1.x, af1.y, af1.z, af1.w };
#pragma unroll
            for (int i = 0; i < 8; ++i) {
                ull ap = pk2(ar[i], ar[i]);
                ffma2(acc[i][0], ap, b0);
                ffma2(acc[i][1], ap, b1);
                ffma2(acc[i][2], ap, b2);
                ffma2(acc[i][3], ap, b3);
            }
        }
        __syncthreads();
    }

    const int na = n0 + tx * 4;
    const int nb = n0 + 64 + tx * 4;
    float bsa[4], bsb[4];
#pragma unroll
    for (int j = 0; j < 4; ++j) {
        bsa[j] = bih[na + j] + bhh[na + j];
        bsb[j] = bih[nb + j] + bhh[nb + j];
    }

#pragma unroll
    for (int i = 0; i < 8; ++i) {
        int t = tbase + ty * 8 + i;
        if (t < lenb) {
            size_t r = (size_t)b * TT + t;
            float v0, v1, v2, v3, v4, v5, v6, v7;
            upk2(acc[i][0], v0, v1); upk2(acc[i][1], v2, v3);
            upk2(acc[i][2], v4, v5); upk2(acc[i][3], v6, v7);
            float4 w0 = make_float4(v0 + bsa[0], v1 + bsa[1], v2 + bsa[2], v3 + bsa[3]);
            float4 w1 = make_float4(v4 + bsb[0], v5 + bsb[1], v6 + bsb[2], v7 + bsb[3]);
            *(float4*)&C[r * G4 + na] = w0;
            *(float4*)&C[r * G4 + nb] = w1;
        }
    }
}

// ---------------------------------------------------------------------------
// LSTM chunk [t0, t1). 1 CTA/batch, 256 threads, 2 gate rows per thread.
// Thread (hh, p): p = lane&1, hh = warp*16 + (lane>>1).
//   rowA = p*128 + hh        (p=0: i-gate, p=1: f-gate)
//   rowB = p*128 + 256 + hh  (p=0: g-gate, p=1: o-gate)
// Columns 0..95 of both rows in registers (96 ull = 192 regs); cols 96..127
// from smem (ulonglong2 per 4-col chunk, slot = tid, conflict-free).
// Gate combine: 2 shfls (f, o from adjacent odd lane). h double-buffered,
// 1 barrier/step. State (c,h,hsum) persisted in global between chunks.
// ---------------------------------------------------------------------------
__global__ void __launch_bounds__(256, 1) lstm_chunk_kernel(
    const float* __restrict__ gates, const float* __restrict__ Whh,
    const int* __restrict__ lens, float* __restrict__ state,
    float* __restrict__ prot, int t0, int t1, int first, int last)
{
    extern __shared__ float sm[];
    float* hb = sm;                                   // [2][128]
    ulonglong2* sWa = (ulonglong2*)(sm + 256);        // [8][256] 32 KB
    ulonglong2* sWb = sWa + 8 * 256;                  // [8][256] 32 KB

    const int b = blockIdx.x;
    const int tid = threadIdx.x;
    const int lane = tid & 31;
    const int p = lane & 1;
    const int hh = (tid >> 5) * 16 + (lane >> 1);
    const int rowA = p * HH + hh;
    const int rowB = p * HH + 256 + hh;

    // register-resident weight cols 0..95 for both rows
    ull wrA[48], wrB[48];
    const float* wpa = Whh + (size_t)rowA * HH;
    const float* wpb = Whh + (size_t)rowB * HH;
#pragma unroll
    for (int j = 0; j < 48; ++j) {
        wrA[j] = *(const ull*)(wpa + 2 * j);
        wrB[j] = *(const ull*)(wpb + 2 * j);
    }
    // smem weight cols 96..127 (each thread its own slot)
#pragma unroll
    for (int q = 0; q < 8; ++q) {
        sWa[q * 256 + tid] = *(const ulonglong2*)(wpa + 96 + 4 * q);
        sWb[q * 256 + tid] = *(const ulonglong2*)(wpb + 96 + 4 * q);
    }

    float* st = state + b * 384;
    if (tid < HH) hb[tid] = first ? 0.f : st[HH + tid];

    float c = 0.f, hsum = 0.f;
    if (p == 0 && !first) { c = st[hh]; hsum = st[256 + hh]; }

    const int len = lens[b];
    const int te = min(len, t1);
    const float* gA = gates + (size_t)b * TT * G4 + rowA;
    const float* gB = gA + 256;
    __syncthreads();

    int buf = 0;
    if (t0 < te) {
        const int tlast = te - 1;
        float gxA = gA[(size_t)t0 * G4];
        float gxB = gB[(size_t)t0 * G4];
        for (int t = t0; t < te; ++t) {
            int tn = (t < tlast) ? t + 1 : tlast;
            float gxAn = gA[(size_t)tn * G4];
            float gxBn = gB[(size_t)tn * G4];

            const ulonglong2* h4 = (const ulonglong2*)(hb + buf * HH);
            ull aA0 = 0ull, aA1 = 0ull, aB0 = 0ull, aB1 = 0ull;
#pragma unroll
            for (int q = 0; q < 24; ++q) {
                ulonglong2 hv = h4[q];
                ffma2(aA0, hv.x, wrA[2 * q]);
                ffma2(aA1, hv.y, wrA[2 * q + 1]);
                ffma2(aB0, hv.x, wrB[2 * q]);
                ffma2(aB1, hv.y, wrB[2 * q + 1]);
            }
#pragma unroll
            for (int q = 0; q < 8; ++q) {
                ulonglong2 hv = h4[24 + q];
                ulonglong2 wa = sWa[q * 256 + tid];
                ulonglong2 wb = sWb[q * 256 + tid];
                ffma2(aA0, hv.x, wa.x);
                ffma2(aA1, hv.y, wa.y);
                ffma2(aB0, hv.x, wb.x);
                ffma2(aB1, hv.y, wb.y);
            }
            float a0l, a0h, a1l, a1h, b0l, b0h, b1l, b1h;
            upk2(aA0, a0l, a0h); upk2(aA1, a1l, a1h);
            upk2(aB0, b0l, b0h); upk2(aB1, b1l, b1h);
            float vA = (a0l + a0h) + (a1l + a1h) + gxA;
            float vB = (b0l + b0h) + (b1l + b1h) + gxB;

            // p=0: xA=i, xB=g ; p=1: xA=f, xB=o
            float xA = sigmoid_fast(vA);
            float xB = (p == 0) ? tanh_fast(vB) : sigmoid_fast(vB);
            float fv = __shfl_sync(0xFFFFFFFFu, xA, lane | 1);
            float ov = __shfl_sync(0xFFFFFFFFu, xB, lane | 1);

            int nbuf = buf ^ 1;
            if (p == 0) {
                c = fv * c + xA * xB;
                float hn = ov * tanh_fast(c);
                hsum += hn;
                hb[nbuf * HH + hh] = hn;
            }
            __syncthreads();
            buf = nbuf;
            gxA = gxAn; gxB = gxBn;
        }
    }

    if (last) {
        if (p == 0) prot[b * 129 + hh] = hsum * (1.f / (float)TT);
        if (tid == 1) prot[b * 129 + HH] = 1.f;
    } else if (p == 0) {
        st[hh] = c;
        st[HH + hh] = hb[buf * HH + hh];
        st[256 + hh] = hsum;
    }
}

// ---------------------------------------------------------------------------
// Generic tiled GEMM: C[M,Nc] = A[M,K] @ W[Nc,K]^T + bias (optional leaky).
// ---------------------------------------------------------------------------
__global__ void gemm_at_kernel(
    const float* __restrict__ A, const float* __restrict__ W,
    const float* __restrict__ bias, float* __restrict__ C,
    int M, int Nc, int K, int ldc, int do_leaky)
{
    __shared__ float As[32][33];
    __shared__ float Ws[32][33];
    const int n0 = blockIdx.x * 32;
    const int m0 = blockIdx.y * 32;
    const int tid = threadIdx.x;
    const int o = tid & 31;
    const int rq = tid >> 5;

    float acc[4] = {0.f, 0.f, 0.f, 0.f};

    for (int k0 = 0; k0 < K; k0 += 32) {
#pragma unroll
        for (int pq = 0; pq < 4; ++pq) {
            int idx = tid + pq * 256;
            int i = idx >> 5;
            int kk = idx & 31;
            int ak = k0 + kk;
            int ar = m0 + i;
            As[i][kk] = (ar < M && ak < K) ? A[(size_t)ar * K + ak] : 0.f;
            int wr_ = n0 + i;
            Ws[i][kk] = (wr_ < Nc && ak < K) ? W[(size_t)wr_ * K + ak] : 0.f;
        }
        __syncthreads();
#pragma unroll
        for (int kk = 0; kk < 32; ++kk) {
            float w = Ws[o][kk];
#pragma unroll
            for (int q = 0; q < 4; ++q)
                acc[q] += As[rq + q * 8][kk] * w;
        }
        __syncthreads();
    }

    int n = n0 + o;
    if (n < Nc) {
        float bv = bias[n];
#pragma unroll
        for (int q = 0; q < 4; ++q) {
            int m = m0 + rq + q * 8;
            if (m < M) {
                float v = acc[q] + bv;
                if (do_leaky) v = leakyf(v);
                C[(size_t)m * ldc + n] = v;
            }
        }
    }
}

// ---------------------------------------------------------------------------
// mix stage A: tmp[r, b] = sum_j mix_W[r*129 + j] * comp[b, j]
// ---------------------------------------------------------------------------
__global__ void __launch_bounds__(256, 2) mixA_kernel(
    const float* __restrict__ W, const float* __restrict__ comp,
    float* __restrict__ tmp)
{
    extern __shared__ float dsm[];
    float* Ws = dsm;              // [128][133]
    float* cs = dsm + 128 * 133;  // [129][32]

    const int tid = threadIdx.x;
    const int r0 = blockIdx.x * 128;

    for (int idx = tid; idx < 129 * 32; idx += 256) {
        int j = idx >> 5;
        int b = idx & 31;
        cs[j * 32 + b] = comp[b * 129 + j];
    }
    const float4* Wp = (const float4*)(W + (size_t)r0 * 129);
    for (int idx = tid; idx < 4128; idx += 256) {
        float4 v = Wp[idx];
        int e = idx * 4;
        float vv[4] = { v.x, v.y, v.z, v.w };
#pragma unroll
        for (int q = 0; q < 4; ++q) {
            int ee = e + q;
            int rr = ee / 129;
            int kk = ee - rr * 129;
            Ws[rr * 133 + kk] = vv[q];
        }
    }
    __syncthreads();

    const int r  = tid >> 1;
    const int bh = (tid & 1) << 4;
    ull acc[8];
#pragma unroll
    for (int q = 0; q < 8; ++q) acc[q] = 0ull;

    const float* wrow = Ws + r * 133;
    for (int k = 0; k < 129; ++k) {
        float w = wrow[k];
        ull wp = pk2(w, w);
        const ull* cp = (const ull*)&cs[k * 32 + bh];
#pragma unroll
        for (int q = 0; q < 8; ++q) ffma2(acc[q], wp, cp[q]);
    }

    float* outp = tmp + (size_t)(r0 + r) * 32 + bh;
#pragma unroll
    for (int q = 0; q < 8; ++q) {
        float lo, hi;
        upk2(acc[q], lo, hi);
        *(float2*)&outp[2 * q] = make_float2(lo, hi);
    }
}

// ---------------------------------------------------------------------------
// mix stage B: out1[b, n] = leaky( sum_i tmp[n*129+i, b] * prot[b, i] + mix_b[n] )
// ---------------------------------------------------------------------------
__global__ void mixB_kernel(
    const float* __restrict__ tmp, const float* __restrict__ prot,
    const float* __restrict__ mix_b, float* __restrict__ out1)
{
    __shared__ float ps[32 * 129];
    __shared__ float part[4][32];
    const int n = blockIdx.x;
    const int tid = threadIdx.x;
    const int lane = tid & 31;
    const int w = tid >> 5;

    for (int idx = tid; idx < 32 * 129; idx += 128) ps[idx] = prot[idx];
    __syncthreads();

    float acc = 0.f;
    const float* tp = tmp + (size_t)n * 129 * 32 + lane;
    const float* pp = ps + lane * 129;
    for (int i = w; i < 129; i += 4)
        acc += tp[i * 32] * pp[i];
    part[w][lane] = acc;
    __syncthreads();
    if (w == 0) {
        float v = part[0][lane] + part[1][lane] + part[2][lane] + part[3][lane] + mix_b[n];
        out1[lane * 1024 + n] = leakyf(v);
    }
}

// ---------------------------------------------------------------------------
// Small kernels
// ---------------------------------------------------------------------------
__global__ void zero_kernel(float* p, int n) {
    int i = blockIdx.x * blockDim.x + threadIdx.x;
    if (i < n) p[i] = 0.f;
}

__global__ void count_kernel(const int* __restrict__ dst, float* __restrict__ cnt) {
    int e = blockIdx.x * blockDim.x + threadIdx.x;
    if (e < EE) atomicAdd(&cnt[dst[e]], 1.f);
}

__global__ void scatter_kernel(const float* __restrict__ x,
                               const int* __restrict__ src, const int* __restrict__ dst,
                               float* __restrict__ msg, int din) {
    int idx = blockIdx.x * blockDim.x + threadIdx.x;
    if (idx >= EE * din) return;
    int e = idx / din;
    int d = idx - e * din;
    atomicAdd(&msg[(size_t)dst[e] * din + d], x[(size_t)src[e] * din + d]);
}

__global__ void build_acat_kernel(const float* __restrict__ msg, const float* __restrict__ cnt,
                                  const float* __restrict__ x, float* __restrict__ acat, int din) {
    int idx = blockIdx.x * blockDim.x + threadIdx.x;
    if (idx >= NN * din) return;
    int n = idx / din;
    int d = idx - n * din;
    float cdiv = fmaxf(cnt[n], 1.f);
    acat[(size_t)n * 2 * din + d] = msg[idx] / cdiv;
    acat[(size_t)n * 2 * din + din + d] = x[idx];
}

__global__ void build_wcat_kernel(const float* __restrict__ Wl, const float* __restrict__ Wr,
                                  float* __restrict__ wcat, int dout, int din) {
    int idx = blockIdx.x * blockDim.x + threadIdx.x;
    if (idx >= dout * din) return;
    int oo = idx / din;
    int d = idx - oo * din;
    wcat[(size_t)oo * 2 * din + d] = Wl[idx];
    wcat[(size_t)oo * 2 * din + din + d] = Wr[idx];
}

__global__ void pool_kernel(const float* __restrict__ x3, float* __restrict__ pool) {
    int idx = blockIdx.x * blockDim.x + threadIdx.x;
    if (idx >= BB * 312) return;
    int b = idx / 312;
    int d = idx - b * 312;
    float m = -3.4e38f;
    int base = b * (NN / BB);
#pragma unroll 4
    for (int n = 0; n < NN / BB; ++n)
        m = fmaxf(m, x3[(size_t)(base + n) * 312 + d]);
    pool[idx] = m;
}

__global__ void set_ones_kernel(float* __restrict__ comp) {
    int t = threadIdx.x;
    if (t < BB) comp[t * 129 + 128] = 1.f;
}

__global__ void cat1_kernel(const float* __restrict__ out1, const float* __restrict__ prot,
                            const float* __restrict__ comp, float* __restrict__ cat1) {
    int idx = blockIdx.x * blockDim.x + threadIdx.x;
    if (idx >= BB * 1282) return;
    int b = idx / 1282;
    int d = idx - b * 1282;
    float v;
    if (d < 1024)       v = out1[b * 1024 + d];
    else if (d < 1153)  v = prot[b * 129 + (d - 1024)];
    else                v = comp[b * 129 + (d - 1153)];
    cat1[idx] = v;
}

__global__ void fc2_kernel(const float* __restrict__ x, const float* __restrict__ W,
                           const float* __restrict__ bias, float* __restrict__ out) {
    __shared__ float red[512];
    int b = blockIdx.x;
    int t = threadIdx.x;
    red[t] = x[(size_t)b * 512 + t] * W[t];
    __syncthreads();
    for (int s = 256; s > 0; s >>= 1) {
        if (t < s) red[t] += red[t + s];
        __syncthreads();
    }
    if (t == 0) out[b] = red[0] + bias[0];
}

// ---------------------------------------------------------------------------
// Launch. s0: gemm chunks -> events. sP: lstm chunks. sB: molecule branch.
// All stream/event resources created ONCE on the first call.
// ---------------------------------------------------------------------------
extern "C" void kernel_launch(void* const* d_in, const int* in_sizes, int n_in,
                              void* d_out, int out_size)
{
    const float* mol_x    = (const float*)d_in[0];
    const float* data_pro = (const float*)d_in[1];
    const int*   ei       = (const int*)d_in[2];
    const int*   lens     = (const int*)d_in[4];
    const float* s1_Wl = (const float*)d_in[5];
    const float* s1_bl = (const float*)d_in[6];
    const float* s1_Wr = (const float*)d_in[7];
    const float* s2_Wl = (const float*)d_in[8];
    const float* s2_bl = (const float*)d_in[9];
    const float* s2_Wr = (const float*)d_in[10];
    const float* s3_Wl = (const float*)d_in[11];
    const float* s3_bl = (const float*)d_in[12];
    const float* s3_Wr = (const float*)d_in[13];
    const float* fcg_W = (const float*)d_in[14];
    const float* fcg_b = (const float*)d_in[15];
    const float* Wih   = (const float*)d_in[16];
    const float* Whh   = (const float*)d_in[17];
    const float* bih   = (const float*)d_in[18];
    const float* bhh   = (const float*)d_in[19];
    const float* mix_W = (const float*)d_in[20];
    const float* mix_b = (const float*)d_in[21];
    const float* fc1_W = (const float*)d_in[22];
    const float* fc1_b = (const float*)d_in[23];
    const float* fc2_W = (const float*)d_in[24];
    const float* fc2_b = (const float*)d_in[25];
    float* out = (float*)d_out;

    float* base = nullptr;
    cudaGetSymbolAddress((void**)&base, g_scratch);
    float* gates = base + OFF_GATES;
    float* msg   = base + OFF_MSG;
    float* cnt   = base + OFF_CNT;
    float* acat  = base + OFF_ACAT;
    float* wcat  = base + OFF_WCAT;
    float* x1    = base + OFF_X1;
    float* x2    = base + OFF_X2;
    float* x3    = base + OFF_X3;
    float* pool  = base + OFF_POOL;
    float* prot  = base + OFF_PROT;
    float* comp  = base + OFF_COMP;
    float* out1  = base + OFF_OUT1;
    float* cat1  = base + OFF_CAT1;
    float* fc1o  = base + OFF_FC1O;
    float* tmpA  = base + OFF_TMP;
    float* state = base + OFF_STATE;

    const int* src = ei;
    const int* dst = ei + EE;

    const int lstm_smem = 256 * 4 + 2 * 8 * 256 * 16;         // 66560 B
    const int mixA_smem = (128 * 133 + 129 * 32) * 4;         // 84608 B

    static cudaStream_t sP = nullptr, sB = nullptr;
    static cudaEvent_t evFork = nullptr, evJoinP = nullptr, evJoinB = nullptr;
    static cudaEvent_t evG[4] = {nullptr, nullptr, nullptr, nullptr};
    if (sP == nullptr) {
        cudaFuncSetAttribute(lstm_chunk_kernel, cudaFuncAttributeMaxDynamicSharedMemorySize, lstm_smem);
        cudaFuncSetAttribute(mixA_kernel, cudaFuncAttributeMaxDynamicSharedMemorySize, mixA_smem);
        cudaStreamCreateWithFlags(&sP, cudaStreamNonBlocking);
        cudaStreamCreateWithFlags(&sB, cudaStreamNonBlocking);
        cudaEventCreateWithFlags(&evFork,  cudaEventDisableTiming);
        cudaEventCreateWithFlags(&evJoinP, cudaEventDisableTiming);
        cudaEventCreateWithFlags(&evJoinB, cudaEventDisableTiming);
        for (int i = 0; i < 4; ++i)
            cudaEventCreateWithFlags(&evG[i], cudaEventDisableTiming);
    }

    // fork molecule stream
    cudaEventRecord(evFork, 0);
    cudaStreamWaitEvent(sB, evFork, 0);

    // --- protein pipeline: gemm chunk k (s0) -> event -> lstm chunk k (sP) ---
    for (int k = 0; k < 4; ++k) {
        gemm_ih_kernel<<<dim3(4, 96), 256>>>(data_pro, Wih, bih, bhh, lens, gates, k * CHUNK_T);
        cudaEventRecord(evG[k], 0);
        cudaStreamWaitEvent(sP, evG[k], 0);
        lstm_chunk_kernel<<<BB, 256, lstm_smem, sP>>>(
            gates, Whh, lens, state, prot,
            k * CHUNK_T, (k == 3) ? TT : (k + 1) * CHUNK_T,
            (k == 0) ? 1 : 0, (k == 3) ? 1 : 0);
    }

    // --- molecule branch + mixA (sB, hidden under protein) ---
    zero_kernel<<<(LEN_MSG + LEN_CNT + 255) / 256, 256, 0, sB>>>(msg, LEN_MSG + LEN_CNT);
    count_kernel<<<(EE + 255) / 256, 256, 0, sB>>>(dst, cnt);
    scatter_kernel<<<(EE * 78 + 255) / 256, 256, 0, sB>>>(mol_x, src, dst, msg, 78);
    build_acat_kernel<<<(NN * 78 + 255) / 256, 256, 0, sB>>>(msg, cnt, mol_x, acat, 78);
    build_wcat_kernel<<<(156 * 78 + 255) / 256, 256, 0, sB>>>(s1_Wl, s1_Wr, wcat, 156, 78);
    gemm_at_kernel<<<dim3(5, 64), 256, 0, sB>>>(acat, wcat, s1_bl, x1, NN, 156, 156, 156, 1);

    zero_kernel<<<(LEN_MSG + 255) / 256, 256, 0, sB>>>(msg, LEN_MSG);
    scatter_kernel<<<(EE * 156 + 255) / 256, 256, 0, sB>>>(x1, src, dst, msg, 156);
    build_acat_kernel<<<(NN * 156 + 255) / 256, 256, 0, sB>>>(msg, cnt, x1, acat, 156);
    build_wcat_kernel<<<(156 * 156 + 255) / 256, 256, 0, sB>>>(s2_Wl, s2_Wr, wcat, 156, 156);
    gemm_at_kernel<<<dim3(5, 64), 256, 0, sB>>>(acat, wcat, s2_bl, x2, NN, 156, 312, 156, 1);

    zero_kernel<<<(LEN_MSG + 255) / 256, 256, 0, sB>>>(msg, LEN_MSG);
    scatter_kernel<<<(EE * 156 + 255) / 256, 256, 0, sB>>>(x2, src, dst, msg, 156);
    build_acat_kernel<<<(NN * 156 + 255) / 256, 256, 0, sB>>>(msg, cnt, x2, acat, 156);
    build_wcat_kernel<<<(312 * 156 + 255) / 256, 256, 0, sB>>>(s3_Wl, s3_Wr, wcat, 312, 156);
    gemm_at_kernel<<<dim3(10, 64), 256, 0, sB>>>(acat, wcat, s3_bl, x3, NN, 312, 312, 312, 1);

    pool_kernel<<<(BB * 312 + 255) / 256, 256, 0, sB>>>(x3, pool);
    gemm_at_kernel<<<dim3(4, 1), 256, 0, sB>>>(pool, fcg_W, fcg_b, comp, BB, 128, 312, 129, 0);
    set_ones_kernel<<<1, 32, 0, sB>>>(comp);
    mixA_kernel<<<1032, 256, mixA_smem, sB>>>(mix_W, comp, tmpA);

    // join both branches into s0
    cudaEventRecord(evJoinP, sP);
    cudaStreamWaitEvent(0, evJoinP, 0);
    cudaEventRecord(evJoinB, sB);
    cudaStreamWaitEvent(0, evJoinB, 0);

    // --- fusion head (s0) ---
    mixB_kernel<<<1024, 128>>>(tmpA, prot, mix_b, out1);
    cat1_kernel<<<(BB * 1282 + 255) / 256, 256>>>(out1, prot, comp, cat1);
    gemm_at_kernel<<<dim3(16, 1), 256>>>(cat1, fc1_W, fc1_b, fc1o, BB, 512, 1282, 512, 1);
    fc2_kernel<<<BB, 512>>>(fc1o, fc2_W, fc2_b, out);
}